// round 2
// baseline (speedup 1.0000x reference)
#include <cuda_runtime.h>
#include <cuda_bf16.h>
#include <stdint.h>

// Problem constants (match reference setup_inputs)
#define N_NODES  100000
#define N_EDGES  3200000
#define D_IN     256
#define D_OUT    256

// ---------------------------------------------------------------------------
// Device-global scratch (allocation-free requirement)
// ---------------------------------------------------------------------------
__device__ float g_support[(size_t)N_NODES * D_OUT];   // ~102.4 MB
__device__ int   g_row_cnt[N_NODES];
__device__ int   g_row_off[N_NODES + 1];
__device__ int   g_row_cur[N_NODES];
__device__ int   g_csr_col[N_EDGES];
__device__ float g_csr_val[N_EDGES];

// ---------------------------------------------------------------------------
// 1) GEMM: support = x @ W   (fp32 SIMT, 128x128x8 tile, 8x8 microtile)
// ---------------------------------------------------------------------------
#define BM 128
#define BN 128
#define BK 8
#define TM 8
#define TN 8

__global__ __launch_bounds__(256, 2)
void gemm_kernel(const float* __restrict__ X, const float* __restrict__ W,
                 float* __restrict__ S, int nrows)
{
    __shared__ float As[BK][BM];   // A stored transposed: As[k][m]
    __shared__ float Bs[BK][BN];

    const int tid = threadIdx.x;            // 0..255
    const int block_row = blockIdx.y * BM;
    const int block_col = blockIdx.x * BN;  // gridDim.x = 2 (D_OUT=256)

    const int tx = tid & 15;                // col group 0..15
    const int ty = tid >> 4;                // row group 0..15

    // A load mapping: 128 rows x 8 k = 256 float4; 2 float4 per row
    const int a_row = tid >> 1;             // 0..127
    const int a_k   = (tid & 1) * 4;        // 0 or 4
    // B load mapping: 8 k x 128 cols = 256 float4
    const int b_k   = tid >> 5;             // 0..7
    const int b_col = (tid & 31) * 4;       // 0..124

    float acc[TM][TN];
    #pragma unroll
    for (int m = 0; m < TM; m++)
        #pragma unroll
        for (int n = 0; n < TN; n++) acc[m][n] = 0.0f;

    for (int k0 = 0; k0 < D_IN; k0 += BK) {
        // Load A tile (guarded rows -> zero)
        float4 av = make_float4(0.f, 0.f, 0.f, 0.f);
        const int gr = block_row + a_row;
        if (gr < nrows)
            av = *reinterpret_cast<const float4*>(X + (size_t)gr * D_IN + k0 + a_k);
        As[a_k + 0][a_row] = av.x;
        As[a_k + 1][a_row] = av.y;
        As[a_k + 2][a_row] = av.z;
        As[a_k + 3][a_row] = av.w;

        // Load B tile
        const float4 bv = *reinterpret_cast<const float4*>(
            W + (size_t)(k0 + b_k) * D_OUT + block_col + b_col);
        *reinterpret_cast<float4*>(&Bs[b_k][b_col]) = bv;

        __syncthreads();

        #pragma unroll
        for (int k = 0; k < BK; k++) {
            float ar[TM], br[TN];
            *reinterpret_cast<float4*>(&ar[0]) =
                *reinterpret_cast<const float4*>(&As[k][ty * TM]);
            *reinterpret_cast<float4*>(&ar[4]) =
                *reinterpret_cast<const float4*>(&As[k][ty * TM + 4]);
            *reinterpret_cast<float4*>(&br[0]) =
                *reinterpret_cast<const float4*>(&Bs[k][tx * TN]);
            *reinterpret_cast<float4*>(&br[4]) =
                *reinterpret_cast<const float4*>(&Bs[k][tx * TN + 4]);
            #pragma unroll
            for (int m = 0; m < TM; m++)
                #pragma unroll
                for (int n = 0; n < TN; n++)
                    acc[m][n] = fmaf(ar[m], br[n], acc[m][n]);
        }
        __syncthreads();
    }

    // Store
    #pragma unroll
    for (int m = 0; m < TM; m++) {
        const int gr = block_row + ty * TM + m;
        if (gr < nrows) {
            float* dst = S + (size_t)gr * D_OUT + block_col + tx * TN;
            *reinterpret_cast<float4*>(dst) =
                make_float4(acc[m][0], acc[m][1], acc[m][2], acc[m][3]);
            *reinterpret_cast<float4*>(dst + 4) =
                make_float4(acc[m][4], acc[m][5], acc[m][6], acc[m][7]);
        }
    }
}

// ---------------------------------------------------------------------------
// 2) CSR build
// ---------------------------------------------------------------------------
__global__ void zero_counts_kernel()
{
    const int i = blockIdx.x * blockDim.x + threadIdx.x;
    if (i < N_NODES) g_row_cnt[i] = 0;
}

__global__ void count_kernel(const int* __restrict__ erow)
{
    const int e = blockIdx.x * blockDim.x + threadIdx.x;
    if (e < N_EDGES) atomicAdd(&g_row_cnt[erow[e]], 1);
}

// Single-block two-level exclusive scan over 100000 counts.
__global__ void scan_kernel()
{
    const int T = 1024;
    const int t = threadIdx.x;
    const int chunk = (N_NODES + T - 1) / T;             // 98
    const int start = t * chunk;
    const int end   = min(start + chunk, N_NODES);

    int sum = 0;
    for (int i = start; i < end; i++) sum += g_row_cnt[i];

    __shared__ int s[T];
    s[t] = sum;
    __syncthreads();

    // Hillis-Steele inclusive scan (read-barrier-write-barrier)
    for (int d = 1; d < T; d <<= 1) {
        int v = (t >= d) ? s[t - d] : 0;
        __syncthreads();
        s[t] += v;
        __syncthreads();
    }

    int run = s[t] - sum;                                // exclusive prefix
    for (int i = start; i < end; i++) {
        const int c = g_row_cnt[i];
        g_row_off[i] = run;
        g_row_cur[i] = run;
        run += c;
    }
    if (end == N_NODES) g_row_off[N_NODES] = run;        // run == total for all such threads
}

__global__ void scatter_kernel(const int* __restrict__ erow,
                               const int* __restrict__ ecol,
                               const float* __restrict__ eval)
{
    const int e = blockIdx.x * blockDim.x + threadIdx.x;
    if (e < N_EDGES) {
        const int r   = erow[e];
        const int pos = atomicAdd(&g_row_cur[r], 1);
        g_csr_col[pos] = ecol[e];
        g_csr_val[pos] = eval[e];
    }
}

// ---------------------------------------------------------------------------
// 3) SpMM: warp-per-row, 8 fp32 accumulators per lane (256 cols/warp)
// ---------------------------------------------------------------------------
__global__ __launch_bounds__(256)
void spmm_kernel(const float* __restrict__ S, float* __restrict__ out)
{
    const int warp = blockIdx.x * (blockDim.x >> 5) + (threadIdx.x >> 5);
    const int lane = threadIdx.x & 31;
    if (warp >= N_NODES) return;

    const int beg = g_row_off[warp];
    const int end = g_row_off[warp + 1];

    float4 a0 = make_float4(0.f, 0.f, 0.f, 0.f);
    float4 a1 = make_float4(0.f, 0.f, 0.f, 0.f);

    for (int e = beg; e < end; e++) {
        const int   c = __ldg(&g_csr_col[e]);      // warp-uniform broadcast
        const float v = __ldg(&g_csr_val[e]);
        const float4* p = reinterpret_cast<const float4*>(S + (size_t)c * D_OUT);
        const float4 s0 = __ldg(p + lane);
        const float4 s1 = __ldg(p + lane + 32);
        a0.x = fmaf(v, s0.x, a0.x); a0.y = fmaf(v, s0.y, a0.y);
        a0.z = fmaf(v, s0.z, a0.z); a0.w = fmaf(v, s0.w, a0.w);
        a1.x = fmaf(v, s1.x, a1.x); a1.y = fmaf(v, s1.y, a1.y);
        a1.z = fmaf(v, s1.z, a1.z); a1.w = fmaf(v, s1.w, a1.w);
    }

    float4* po = reinterpret_cast<float4*>(out + (size_t)warp * D_OUT);
    po[lane]      = a0;
    po[lane + 32] = a1;
}

// ---------------------------------------------------------------------------
// Launch
// ---------------------------------------------------------------------------
extern "C" void kernel_launch(void* const* d_in, const int* in_sizes, int n_in,
                              void* d_out, int out_size)
{
    const float* x      = (const float*)d_in[0];
    const float* weight = (const float*)d_in[1];
    const int*   erow   = (const int*)  d_in[2];
    const int*   ecol   = (const int*)  d_in[3];
    const float* eval   = (const float*)d_in[4];
    float*       out    = (float*)d_out;

    float* support;
    cudaGetSymbolAddress((void**)&support, g_support);

    // CSR build
    zero_counts_kernel<<<(N_NODES + 255) / 256, 256>>>();
    count_kernel<<<(N_EDGES + 255) / 256, 256>>>(erow);
    scan_kernel<<<1, 1024>>>();
    scatter_kernel<<<(N_EDGES + 255) / 256, 256>>>(erow, ecol, eval);

    // GEMM: support = x @ W
    dim3 ggrid(D_OUT / BN, (N_NODES + BM - 1) / BM);
    gemm_kernel<<<ggrid, 256>>>(x, weight, support, N_NODES);

    // SpMM: out = A * support (warp per row)
    const int warps_per_block = 256 / 32;
    spmm_kernel<<<(N_NODES + warps_per_block - 1) / warps_per_block, 256>>>(support, out);
}